// round 14
// baseline (speedup 1.0000x reference)
#include <cuda_runtime.h>
#include <cuda_fp16.h>
#include <cstdint>

#define E_EXPERTS 8
#define H_DIM 2048
#define I_DIM 1024
#define T_TOK 16384

// ---------------- device scratch (allocation-free rule) ----------------
__device__ __half a_h[(size_t)T_TOK * H_DIM];                  // fp16 activations
__device__ __half u_s[(size_t)T_TOK * I_DIM];                  // up-proj result
__device__ __half g_s[(size_t)T_TOK * I_DIM];                  // gate-proj result
__device__ __half h_s[(size_t)T_TOK * I_DIM];                  // swiglu output
__device__ __half gate_h[(size_t)E_EXPERTS * H_DIM * I_DIM];   // fp16 weights [E][K][N]
__device__ __half up_h[(size_t)E_EXPERTS * H_DIM * I_DIM];
__device__ __half down_h[(size_t)E_EXPERTS * H_DIM * I_DIM];

// ---------------- helpers ----------------
__device__ __forceinline__ uint32_t smem_u32(const void* p) {
    return (uint32_t)__cvta_generic_to_shared(p);
}
__device__ __forceinline__ void cp_async16(uint32_t dst, const void* src) {
    asm volatile("cp.async.cg.shared.global [%0], [%1], 16;" :: "r"(dst), "l"(src) : "memory");
}
__device__ __forceinline__ void ldsm_x4(uint32_t* r, uint32_t addr) {
    asm volatile("ldmatrix.sync.aligned.m8n8.x4.shared.b16 {%0,%1,%2,%3}, [%4];"
                 : "=r"(r[0]), "=r"(r[1]), "=r"(r[2]), "=r"(r[3]) : "r"(addr));
}
__device__ __forceinline__ void ldsm_x4_t(uint32_t* r, uint32_t addr) {
    asm volatile("ldmatrix.sync.aligned.m8n8.x4.trans.shared.b16 {%0,%1,%2,%3}, [%4];"
                 : "=r"(r[0]), "=r"(r[1]), "=r"(r[2]), "=r"(r[3]) : "r"(addr));
}
__device__ __forceinline__ void mma_f16(float* d, const uint32_t* a, const uint32_t* b) {
    asm volatile(
        "mma.sync.aligned.m16n8k16.row.col.f32.f16.f16.f32 "
        "{%0,%1,%2,%3}, {%4,%5,%6,%7}, {%8,%9}, {%0,%1,%2,%3};"
        : "+f"(d[0]), "+f"(d[1]), "+f"(d[2]), "+f"(d[3])
        : "r"(a[0]), "r"(a[1]), "r"(a[2]), "r"(a[3]), "r"(b[0]), "r"(b[1]));
}

// ---------------- prepass: fp32 -> fp16 (RN) ----------------
__global__ void f2h_kernel(const float4* __restrict__ in, uint2* __restrict__ out, int n4) {
    int i = blockIdx.x * blockDim.x + threadIdx.x;
    if (i < n4) {
        float4 v = in[i];
        __half2 h0 = __floats2half2_rn(v.x, v.y);
        __half2 h1 = __floats2half2_rn(v.z, v.w);
        uint2 o;
        o.x = *(uint32_t*)&h0;
        o.y = *(uint32_t*)&h1;
        out[i] = o;
    }
}

__global__ void f2h3_kernel(const float4* __restrict__ in0, uint2* __restrict__ out0,
                            const float4* __restrict__ in1, uint2* __restrict__ out1,
                            const float4* __restrict__ in2, uint2* __restrict__ out2,
                            int n4) {
    int i = blockIdx.x * blockDim.x + threadIdx.x;
    if (i >= n4) return;
    const float4* in = (blockIdx.y == 0) ? in0 : (blockIdx.y == 1) ? in1 : in2;
    uint2* out = (blockIdx.y == 0) ? out0 : (blockIdx.y == 1) ? out1 : out2;
    float4 v = in[i];
    __half2 h0 = __floats2half2_rn(v.x, v.y);
    __half2 h1 = __floats2half2_rn(v.z, v.w);
    uint2 o;
    o.x = *(uint32_t*)&h0;
    o.y = *(uint32_t*)&h1;
    out[i] = o;
}

// ---------------- swiglu elementwise: h = rn16(silu(g) * u) ----------------
__global__ void swiglu_kernel(const uint2* __restrict__ g, const uint2* __restrict__ u,
                              uint2* __restrict__ h, int n4) {
    int i = blockIdx.x * blockDim.x + threadIdx.x;
    if (i >= n4) return;
    uint2 gv = g[i], uv = u[i];
    float2 g0 = __half22float2(*(const __half2*)&gv.x);
    float2 g1 = __half22float2(*(const __half2*)&gv.y);
    float2 u0 = __half22float2(*(const __half2*)&uv.x);
    float2 u1 = __half22float2(*(const __half2*)&uv.y);
    float h0 = g0.x / (1.f + __expf(-g0.x)) * u0.x;
    float h1 = g0.y / (1.f + __expf(-g0.y)) * u0.y;
    float h2 = g1.x / (1.f + __expf(-g1.x)) * u1.x;
    float h3 = g1.y / (1.f + __expf(-g1.y)) * u1.y;
    __half2 o0 = __floats2half2_rn(h0, h1);
    __half2 o1 = __floats2half2_rn(h2, h3);
    uint2 o;
    o.x = *(uint32_t*)&o0;
    o.y = *(uint32_t*)&o1;
    h[i] = o;
}

// -----------------------------------------------------------------------------
// Grouped GEMM via mma.sync fp16 (m16n8k16, f32 accum).
// NEW occupancy point: CTA 128x128 with 128 threads = 4 warps (2M x 2N),
// warp tile 64x64, BK=32, S=3 -> 56.8 KB smem -> 3 CTA/SM (12 warps/SM).
// Crossbar drops to 75% of tensor-busy -> tensor pipe becomes the binder.
// B fragments loaded in two 8-reg phases to hold regs <= 168 (cap @ occ 3).
// blockIdx.z selects (B0,C0)/(B1,C1) for the combined up+gate launch.
// MODE 0: C fp16 raw. MODE 2: C fp32 raw.
// -----------------------------------------------------------------------------
template <int MODE>
__global__ __launch_bounds__(128, 3)
void mma_gemm(const __half* __restrict__ A,
              const __half* __restrict__ B0w, const __half* __restrict__ B1w,
              const int* __restrict__ gsz,
              void* __restrict__ C0v, void* __restrict__ C1v, int K, int N) {
    constexpr int BM = 128, BN = 128, BK = 32, S = 3;
    constexpr int APAD = 40;                 // halves (80B rows)
    constexpr int BPAD = BN + 8;             // 136 halves (272B rows)
    constexpr int A_HL = BM * APAD;          // 5120 halves
    constexpr int B_HL = BK * BPAD;          // 4352 halves
    constexpr int STAGE = A_HL + B_HL;       // 9472 halves = 18944 B

    extern __shared__ __half smh[];
    __shared__ int bound[E_EXPERTS + 1];

    const __half* Bw = blockIdx.z ? B1w : B0w;
    void* Cv = blockIdx.z ? C1v : C0v;

    const int tid = threadIdx.x;
    const int wid = tid >> 5;
    const int lane = tid & 31;
    const int wm = wid & 1;                  // 2 warp-rows of 64
    const int wn = wid >> 1;                 // 2 warp-cols of 64
    const int lr = lane >> 2;                // 0..7
    const int lc = lane & 3;                 // 0..3
    const int l16 = lane & 15;
    const int lh8 = (lane >> 4) << 3;

    if (tid == 0) {
        int acc = 0;
        bound[0] = 0;
        #pragma unroll
        for (int e = 0; e < E_EXPERTS; e++) { acc += gsz[e]; bound[e + 1] = acc; }
    }
    __syncthreads();

    const int m0 = blockIdx.y * BM;
    const int n0 = blockIdx.x * BN;
    const int nch = K / BK;
    const uint32_t sm_u = smem_u32(smh);

    int row = m0;
    while (row < m0 + BM) {
        int e = 0;
        while (bound[e + 1] <= row) e++;
        const int seg_end = bound[e + 1] < m0 + BM ? bound[e + 1] : m0 + BM;
        const __half* Be = Bw + (size_t)e * K * N;

        float acc[4][8][4];                  // [ma][na][quad] = 128 regs
        #pragma unroll
        for (int ma = 0; ma < 4; ma++)
            #pragma unroll
            for (int na = 0; na < 8; na++)
                #pragma unroll
                for (int q = 0; q < 4; q++) acc[ma][na][q] = 0.f;

        auto load_stage = [&](int c) {
            int s = c % S;
            __half* as = smh + s * STAGE;
            int kc = c * BK;
            // A tile: 128 rows x 32 halves = 512 x 16B chunks, 4/thread
            #pragma unroll
            for (int i = 0; i < 4; i++) {
                int idx = tid + i * 128;
                int m = idx >> 2, cc = (idx & 3) << 3;
                cp_async16(smem_u32(as + m * APAD + cc),
                           A + (size_t)(m0 + m) * K + kc + cc);
            }
            // B tile: 32 rows x 128 halves = 512 x 16B chunks, 4/thread
            __half* bs = as + A_HL;
            #pragma unroll
            for (int i = 0; i < 4; i++) {
                int idx = tid + i * 128;
                int kr = idx >> 4, nc = (idx & 15) << 3;
                cp_async16(smem_u32(bs + kr * BPAD + nc),
                           Be + (size_t)(kc + kr) * N + n0 + nc);
            }
            asm volatile("cp.async.commit_group;" ::: "memory");
        };

        #pragma unroll
        for (int c = 0; c < S - 1; c++) load_stage(c);

        for (int c = 0; c < nch; c++) {
            asm volatile("cp.async.wait_group %0;" :: "n"(S - 2));
            __syncthreads();
            if (c + S - 1 < nch) load_stage(c + S - 1);
            else asm volatile("cp.async.commit_group;" ::: "memory");

            const uint32_t as_u = sm_u + (uint32_t)((c % S) * STAGE) * 2u;
            const uint32_t bs_u = as_u + (uint32_t)A_HL * 2u;
            const uint32_t aA = as_u + (uint32_t)((wm * 64 + l16) * APAD + lh8) * 2u;
            const uint32_t bB = bs_u + (uint32_t)(l16 * BPAD + wn * 64 + lh8) * 2u;

            #pragma unroll
            for (int ks = 0; ks < 2; ks++) {          // two K=16 slabs
                const int k0 = ks * 16;
                uint32_t af[4][4];
                #pragma unroll
                for (int ma = 0; ma < 4; ma++)
                    ldsm_x4(af[ma], aA + (uint32_t)(ma * 16 * APAD + k0) * 2u);
                // B in two phases of 32 cols (8 regs) to cap register pressure
                #pragma unroll
                for (int ph = 0; ph < 2; ph++) {
                    uint32_t bq[2][4];
                    #pragma unroll
                    for (int g = 0; g < 2; g++)
                        ldsm_x4_t(bq[g], bB + (uint32_t)(k0 * BPAD + (ph * 2 + g) * 16) * 2u);
                    #pragma unroll
                    for (int nl = 0; nl < 4; nl++) {
                        const int na = ph * 4 + nl;
                        const uint32_t* bf = &bq[nl >> 1][(nl & 1) << 1];
                        #pragma unroll
                        for (int ma = 0; ma < 4; ma++)
                            mma_f16(acc[ma][na], af[ma], bf);
                    }
                }
            }
        }

        // ---------------- epilogue ----------------
        #pragma unroll
        for (int ma = 0; ma < 4; ma++) {
            int r1 = m0 + wm * 64 + ma * 16 + lr;
            int r2 = r1 + 8;
            bool a1 = (r1 >= row && r1 < seg_end);
            bool a2 = (r2 >= row && r2 < seg_end);
            #pragma unroll
            for (int na = 0; na < 8; na++) {
                int col = n0 + wn * 64 + na * 8 + 2 * lc;
                float g0 = acc[ma][na][0], g1 = acc[ma][na][1];
                float g2 = acc[ma][na][2], g3 = acc[ma][na][3];
                if (MODE == 0) {
                    __half* C = (__half*)Cv;
                    if (a1) *(__half2*)(C + (size_t)r1 * N + col) = __floats2half2_rn(g0, g1);
                    if (a2) *(__half2*)(C + (size_t)r2 * N + col) = __floats2half2_rn(g2, g3);
                } else {
                    float* C = (float*)Cv;
                    if (a1) *(float2*)(C + (size_t)r1 * N + col) = make_float2(g0, g1);
                    if (a2) *(float2*)(C + (size_t)r2 * N + col) = make_float2(g2, g3);
                }
            }
        }
        __syncthreads();   // protect smem ring across segments / tail cp.asyncs
        row = seg_end;
    }
}

// ---------------- launch ----------------
extern "C" void kernel_launch(void* const* d_in, const int* in_sizes, int n_in,
                              void* d_out, int out_size) {
    (void)in_sizes; (void)n_in; (void)out_size;
    const float* hidden = (const float*)d_in[0];
    const float* gate_w = (const float*)d_in[1];
    const float* up_w   = (const float*)d_in[2];
    const float* down_w = (const float*)d_in[3];
    const int*   gs     = (const int*)d_in[4];
    float* out = (float*)d_out;

    __half *aP, *uP, *gsP, *hP, *gP, *upP, *dP;
    cudaGetSymbolAddress((void**)&aP, a_h);
    cudaGetSymbolAddress((void**)&uP, u_s);
    cudaGetSymbolAddress((void**)&gsP, g_s);
    cudaGetSymbolAddress((void**)&hP, h_s);
    cudaGetSymbolAddress((void**)&gP, gate_h);
    cudaGetSymbolAddress((void**)&upP, up_h);
    cudaGetSymbolAddress((void**)&dP, down_h);

    constexpr int SMEM = 3 * (5120 + 4352) * 2;   // 56,832 B -> 3 CTA/SM
    cudaFuncSetAttribute((const void*)mma_gemm<0>,
                         cudaFuncAttributeMaxDynamicSharedMemorySize, SMEM);
    cudaFuncSetAttribute((const void*)mma_gemm<2>,
                         cudaFuncAttributeMaxDynamicSharedMemorySize, SMEM);

    // prepass: fp32 -> fp16
    int nA4 = (int)((size_t)T_TOK * H_DIM / 4);
    int nW4 = (int)((size_t)E_EXPERTS * H_DIM * I_DIM / 4);
    f2h_kernel<<<(nA4 + 255) / 256, 256>>>((const float4*)hidden, (uint2*)aP, nA4);
    f2h3_kernel<<<dim3((nW4 + 255) / 256, 3), 256>>>(
        (const float4*)gate_w, (uint2*)gP,
        (const float4*)up_w,   (uint2*)upP,
        (const float4*)down_w, (uint2*)dP, nW4);

    // 1) up + gate projections in ONE launch (z=0: u, z=1: g)
    mma_gemm<0><<<dim3(I_DIM / 128, T_TOK / 128, 2), 128, SMEM>>>(
        aP, upP, gP, gs, uP, gsP, H_DIM, I_DIM);

    // 2) SwiGLU elementwise: h = rn16(silu(g) * u)
    int nH4 = (int)((size_t)T_TOK * I_DIM / 4);
    swiglu_kernel<<<(nH4 + 255) / 256, 256>>>((const uint2*)gsP, (const uint2*)uP,
                                              (uint2*)hP, nH4);

    // 3) down-projection: out = h @ down_w (fp32 out)
    mma_gemm<2><<<dim3(H_DIM / 128, T_TOK / 128, 1), 128, SMEM>>>(
        hP, dP, dP, gs, out, out, I_DIM, H_DIM);
}

// round 15
// speedup vs baseline: 1.0491x; 1.0491x over previous
#include <cuda_runtime.h>
#include <cuda_fp16.h>
#include <cstdint>

#define E_EXPERTS 8
#define H_DIM 2048
#define I_DIM 1024
#define T_TOK 16384

// ---------------- device scratch (allocation-free rule) ----------------
__device__ __half a_h[(size_t)T_TOK * H_DIM];                  // fp16 activations
__device__ __half u_s[(size_t)T_TOK * I_DIM];                  // up-proj result
__device__ __half g_s[(size_t)T_TOK * I_DIM];                  // gate-proj result
__device__ __half h_s[(size_t)T_TOK * I_DIM];                  // swiglu output
__device__ __half gate_h[(size_t)E_EXPERTS * H_DIM * I_DIM];   // fp16 weights [E][K][N]
__device__ __half up_h[(size_t)E_EXPERTS * H_DIM * I_DIM];
__device__ __half down_h[(size_t)E_EXPERTS * H_DIM * I_DIM];

// ---------------- helpers ----------------
__device__ __forceinline__ uint32_t smem_u32(const void* p) {
    return (uint32_t)__cvta_generic_to_shared(p);
}
__device__ __forceinline__ void cp_async16(uint32_t dst, const void* src) {
    asm volatile("cp.async.cg.shared.global [%0], [%1], 16;" :: "r"(dst), "l"(src) : "memory");
}
__device__ __forceinline__ void ldsm_x4(uint32_t* r, uint32_t addr) {
    asm volatile("ldmatrix.sync.aligned.m8n8.x4.shared.b16 {%0,%1,%2,%3}, [%4];"
                 : "=r"(r[0]), "=r"(r[1]), "=r"(r[2]), "=r"(r[3]) : "r"(addr));
}
__device__ __forceinline__ void ldsm_x4_t(uint32_t* r, uint32_t addr) {
    asm volatile("ldmatrix.sync.aligned.m8n8.x4.trans.shared.b16 {%0,%1,%2,%3}, [%4];"
                 : "=r"(r[0]), "=r"(r[1]), "=r"(r[2]), "=r"(r[3]) : "r"(addr));
}
__device__ __forceinline__ void mma_f16(float* d, const uint32_t* a, const uint32_t* b) {
    asm volatile(
        "mma.sync.aligned.m16n8k16.row.col.f32.f16.f16.f32 "
        "{%0,%1,%2,%3}, {%4,%5,%6,%7}, {%8,%9}, {%0,%1,%2,%3};"
        : "+f"(d[0]), "+f"(d[1]), "+f"(d[2]), "+f"(d[3])
        : "r"(a[0]), "r"(a[1]), "r"(a[2]), "r"(a[3]), "r"(b[0]), "r"(b[1]));
}
__device__ __forceinline__ uint2 cvt4(float4 v) {
    __half2 h0 = __floats2half2_rn(v.x, v.y);
    __half2 h1 = __floats2half2_rn(v.z, v.w);
    uint2 o;
    o.x = *(uint32_t*)&h0;
    o.y = *(uint32_t*)&h1;
    return o;
}

// ---------------- prepass: fp32 -> fp16 (RN) ----------------
__global__ void f2h_kernel(const float4* __restrict__ in, uint2* __restrict__ out, int n4) {
    int i = blockIdx.x * blockDim.x + threadIdx.x;
    if (i < n4) out[i] = cvt4(in[i]);
}

// gate + up only (down conversion folded into GEMM-1's z=2 slice)
__global__ void f2h2_kernel(const float4* __restrict__ in0, uint2* __restrict__ out0,
                            const float4* __restrict__ in1, uint2* __restrict__ out1,
                            int n4) {
    int i = blockIdx.x * blockDim.x + threadIdx.x;
    if (i >= n4) return;
    const float4* in = (blockIdx.y == 0) ? in0 : in1;
    uint2* out = (blockIdx.y == 0) ? out0 : out1;
    out[i] = cvt4(in[i]);
}

// ---------------- swiglu elementwise: h = rn16(silu(g) * u) ----------------
__global__ void swiglu_kernel(const uint2* __restrict__ g, const uint2* __restrict__ u,
                              uint2* __restrict__ h, int n4) {
    int i = blockIdx.x * blockDim.x + threadIdx.x;
    if (i >= n4) return;
    uint2 gv = g[i], uv = u[i];
    float2 g0 = __half22float2(*(const __half2*)&gv.x);
    float2 g1 = __half22float2(*(const __half2*)&gv.y);
    float2 u0 = __half22float2(*(const __half2*)&uv.x);
    float2 u1 = __half22float2(*(const __half2*)&uv.y);
    float h0 = g0.x / (1.f + __expf(-g0.x)) * u0.x;
    float h1 = g0.y / (1.f + __expf(-g0.y)) * u0.y;
    float h2 = g1.x / (1.f + __expf(-g1.x)) * u1.x;
    float h3 = g1.y / (1.f + __expf(-g1.y)) * u1.y;
    __half2 o0 = __floats2half2_rn(h0, h1);
    __half2 o1 = __floats2half2_rn(h2, h3);
    uint2 o;
    o.x = *(uint32_t*)&o0;
    o.y = *(uint32_t*)&o1;
    h[i] = o;
}

// -----------------------------------------------------------------------------
// Grouped GEMM via mma.sync fp16 (m16n8k16, f32 accum). Round-13 champion
// config verbatim: CTA 128x128, 256 threads = 8 warps (2M x 4N), warp tile
// 64x32, BK=64, S=3, 2 CTA/SM. blockIdx.z: 0 -> (B0w,C0), 1 -> (B1w,C1),
// 2 -> pure fp32->fp16 conversion slice (cvt_in -> cvt_out; rides GEMM-1's
// tail waves for free since DRAM is ~7% busy during the GEMM).
// MODE 0: C fp16 raw. MODE 2: C fp32 raw.
// -----------------------------------------------------------------------------
template <int MODE>
__global__ __launch_bounds__(256, 2)
void mma_gemm(const __half* __restrict__ A,
              const __half* __restrict__ B0w, const __half* __restrict__ B1w,
              const int* __restrict__ gsz,
              void* __restrict__ C0v, void* __restrict__ C1v,
              const float4* __restrict__ cvt_in, uint2* __restrict__ cvt_out,
              int K, int N) {
    constexpr int BM = 128, BN = 128, BK = 64, S = 3;
    constexpr int APAD = 72;                 // 64 halves + 8 pad (144B rows)
    constexpr int BPAD = BN + 8;             // 136 halves (272B rows)
    constexpr int A_HL = BM * APAD;          // 9216 halves
    constexpr int B_HL = BK * BPAD;          // 8704 halves
    constexpr int STAGE = A_HL + B_HL;       // 17920 halves = 35840 B

    // conversion slice: 1024 CTAs x 256 threads x 16 uint2 = 4,194,304 uint2
    if (blockIdx.z == 2) {
        int bid = blockIdx.y * gridDim.x + blockIdx.x;      // 0..1023
        int base = bid * 4096 + threadIdx.x;
        #pragma unroll
        for (int i = 0; i < 16; i++)
            cvt_out[base + i * 256] = cvt4(cvt_in[base + i * 256]);
        return;
    }

    extern __shared__ __half smh[];
    __shared__ int bound[E_EXPERTS + 1];

    const __half* Bw = blockIdx.z ? B1w : B0w;
    void* Cv = blockIdx.z ? C1v : C0v;

    const int tid = threadIdx.x;
    const int wid = tid >> 5;
    const int lane = tid & 31;
    const int wm = wid & 1;                  // 2 warp-rows of 64
    const int wn = wid >> 1;                 // 4 warp-cols of 32
    const int lr = lane >> 2;                // 0..7
    const int lc = lane & 3;                 // 0..3
    const int l16 = lane & 15;
    const int lh8 = (lane >> 4) << 3;

    if (tid == 0) {
        int acc = 0;
        bound[0] = 0;
        #pragma unroll
        for (int e = 0; e < E_EXPERTS; e++) { acc += gsz[e]; bound[e + 1] = acc; }
    }
    __syncthreads();

    const int m0 = blockIdx.y * BM;
    const int n0 = blockIdx.x * BN;
    const int nch = K / BK;
    const uint32_t sm_u = smem_u32(smh);

    int row = m0;
    while (row < m0 + BM) {
        int e = 0;
        while (bound[e + 1] <= row) e++;
        const int seg_end = bound[e + 1] < m0 + BM ? bound[e + 1] : m0 + BM;
        const __half* Be = Bw + (size_t)e * K * N;

        float acc[4][4][4];                  // 64 regs
        #pragma unroll
        for (int ma = 0; ma < 4; ma++)
            #pragma unroll
            for (int na = 0; na < 4; na++)
                #pragma unroll
                for (int q = 0; q < 4; q++) acc[ma][na][q] = 0.f;

        auto load_stage = [&](int c) {
            int s = c % S;
            __half* as = smh + s * STAGE;
            int kc = c * BK;
            // A tile: 128 rows x 64 halves (128B/row) = 1024 x 16B, 4/thread
            #pragma unroll
            for (int i = 0; i < 4; i++) {
                int idx = tid + i * 256;
                int m = idx >> 3, cc = (idx & 7) << 3;
                cp_async16(smem_u32(as + m * APAD + cc),
                           A + (size_t)(m0 + m) * K + kc + cc);
            }
            // B tile: 64 rows x 128 halves (256B/row) = 1024 x 16B, 4/thread
            __half* bs = as + A_HL;
            #pragma unroll
            for (int i = 0; i < 4; i++) {
                int idx = tid + i * 256;
                int kr = idx >> 4, nc = (idx & 15) << 3;
                cp_async16(smem_u32(bs + kr * BPAD + nc),
                           Be + (size_t)(kc + kr) * N + n0 + nc);
            }
            asm volatile("cp.async.commit_group;" ::: "memory");
        };

        #pragma unroll
        for (int c = 0; c < S - 1; c++) load_stage(c);

        for (int c = 0; c < nch; c++) {
            asm volatile("cp.async.wait_group %0;" :: "n"(S - 2));
            __syncthreads();
            if (c + S - 1 < nch) load_stage(c + S - 1);
            else asm volatile("cp.async.commit_group;" ::: "memory");

            const uint32_t as_u = sm_u + (uint32_t)((c % S) * STAGE) * 2u;
            const uint32_t bs_u = as_u + (uint32_t)A_HL * 2u;
            const uint32_t aA = as_u + (uint32_t)((wm * 64 + l16) * APAD + lh8) * 2u;
            const uint32_t bB = bs_u + (uint32_t)(l16 * BPAD + wn * 32 + lh8) * 2u;

            #pragma unroll
            for (int ks = 0; ks < 4; ks++) {          // four K=16 slabs
                const int k0 = ks * 16;
                uint32_t af[4][4];
                #pragma unroll
                for (int ma = 0; ma < 4; ma++)
                    ldsm_x4(af[ma], aA + (uint32_t)(ma * 16 * APAD + k0) * 2u);
                uint32_t bq[2][4];
                #pragma unroll
                for (int g = 0; g < 2; g++)
                    ldsm_x4_t(bq[g], bB + (uint32_t)(k0 * BPAD + g * 16) * 2u);
                #pragma unroll
                for (int na = 0; na < 4; na++) {
                    const uint32_t* bf = &bq[na >> 1][(na & 1) << 1];
                    #pragma unroll
                    for (int ma = 0; ma < 4; ma++)
                        mma_f16(acc[ma][na], af[ma], bf);
                }
            }
        }

        // ---------------- epilogue ----------------
        #pragma unroll
        for (int ma = 0; ma < 4; ma++) {
            int r1 = m0 + wm * 64 + ma * 16 + lr;
            int r2 = r1 + 8;
            bool a1 = (r1 >= row && r1 < seg_end);
            bool a2 = (r2 >= row && r2 < seg_end);
            #pragma unroll
            for (int na = 0; na < 4; na++) {
                int col = n0 + wn * 32 + na * 8 + 2 * lc;
                float g0 = acc[ma][na][0], g1 = acc[ma][na][1];
                float g2 = acc[ma][na][2], g3 = acc[ma][na][3];
                if (MODE == 0) {
                    __half* C = (__half*)Cv;
                    if (a1) *(__half2*)(C + (size_t)r1 * N + col) = __floats2half2_rn(g0, g1);
                    if (a2) *(__half2*)(C + (size_t)r2 * N + col) = __floats2half2_rn(g2, g3);
                } else {
                    float* C = (float*)Cv;
                    if (a1) *(float2*)(C + (size_t)r1 * N + col) = make_float2(g0, g1);
                    if (a2) *(float2*)(C + (size_t)r2 * N + col) = make_float2(g2, g3);
                }
            }
        }
        __syncthreads();   // protect smem ring across segments / tail cp.asyncs
        row = seg_end;
    }
}

// ---------------- launch ----------------
extern "C" void kernel_launch(void* const* d_in, const int* in_sizes, int n_in,
                              void* d_out, int out_size) {
    (void)in_sizes; (void)n_in; (void)out_size;
    const float* hidden = (const float*)d_in[0];
    const float* gate_w = (const float*)d_in[1];
    const float* up_w   = (const float*)d_in[2];
    const float* down_w = (const float*)d_in[3];
    const int*   gs     = (const int*)d_in[4];
    float* out = (float*)d_out;

    __half *aP, *uP, *gsP, *hP, *gP, *upP, *dP;
    cudaGetSymbolAddress((void**)&aP, a_h);
    cudaGetSymbolAddress((void**)&uP, u_s);
    cudaGetSymbolAddress((void**)&gsP, g_s);
    cudaGetSymbolAddress((void**)&hP, h_s);
    cudaGetSymbolAddress((void**)&gP, gate_h);
    cudaGetSymbolAddress((void**)&upP, up_h);
    cudaGetSymbolAddress((void**)&dP, down_h);

    constexpr int SMEM = 3 * (9216 + 8704) * 2;   // 107,520 B -> 2 CTA/SM
    cudaFuncSetAttribute((const void*)mma_gemm<0>,
                         cudaFuncAttributeMaxDynamicSharedMemorySize, SMEM);
    cudaFuncSetAttribute((const void*)mma_gemm<2>,
                         cudaFuncAttributeMaxDynamicSharedMemorySize, SMEM);

    // prepass: activations + gate/up weights (down weights convert inside GEMM-1)
    int nA4 = (int)((size_t)T_TOK * H_DIM / 4);
    int nW4 = (int)((size_t)E_EXPERTS * H_DIM * I_DIM / 4);
    f2h_kernel<<<(nA4 + 255) / 256, 256>>>((const float4*)hidden, (uint2*)aP, nA4);
    f2h2_kernel<<<dim3((nW4 + 255) / 256, 2), 256>>>(
        (const float4*)gate_w, (uint2*)gP,
        (const float4*)up_w,   (uint2*)upP, nW4);

    // 1) up + gate projections + down-weight conversion in ONE launch
    //    (z=0: u, z=1: g, z=2: down_w fp32->fp16 riding the tail waves)
    mma_gemm<0><<<dim3(I_DIM / 128, T_TOK / 128, 3), 256, SMEM>>>(
        aP, upP, gP, gs, uP, gsP, (const float4*)down_w, (uint2*)dP, H_DIM, I_DIM);

    // 2) SwiGLU elementwise: h = rn16(silu(g) * u)
    int nH4 = (int)((size_t)T_TOK * I_DIM / 4);
    swiglu_kernel<<<(nH4 + 255) / 256, 256>>>((const uint2*)gsP, (const uint2*)uP,
                                              (uint2*)hP, nH4);

    // 3) down-projection: out = h @ down_w (fp32 out)
    mma_gemm<2><<<dim3(H_DIM / 128, T_TOK / 128, 1), 256, SMEM>>>(
        hP, dP, dP, gs, out, out, nullptr, nullptr, I_DIM, H_DIM);
}